// round 1
// baseline (speedup 1.0000x reference)
#include <cuda_runtime.h>

// Problem constants
#define B 32
#define L 6
#define R 8
#define H 64
#define NTRAJ 262144            // R^L
#define F4_PER_B 393216         // NTRAJ * L / 4

// Scratch for the 1536 MLP outputs q0[b][l][r] (allowed: __device__ global)
__device__ float g_q0[B * L * R];

// ---------------------------------------------------------------------------
// Kernel 1: tiny MLP. One block per (b,l,r) element, 64 threads = H lanes.
//   h1[j] = relu(W1[j][0]*x + W1[j][1]*p + b1[j])
//   h2[g] = relu(W2[g]·h1 + b2[g])
//   q0    = W3[0]·h2 + b3[0]
// ---------------------------------------------------------------------------
__global__ void __launch_bounds__(64) zdec_mlp_kernel(
    const float* __restrict__ phi,   // (B, L)
    const float* __restrict__ rp,    // (L, R, 1)
    const float* __restrict__ W1,    // (H, 2)
    const float* __restrict__ b1,    // (H,)
    const float* __restrict__ W2,    // (H, H)
    const float* __restrict__ b2,    // (H,)
    const float* __restrict__ W3,    // (OUT, H) — only row 0 used
    const float* __restrict__ b3)    // (OUT,)  — only [0] used
{
    const int i  = blockIdx.x;          // 0 .. 1535, i = b*48 + l*8 + r
    const int b  = i / (L * R);
    const int lr = i % (L * R);
    const int l  = lr / R;
    const int j  = threadIdx.x;         // hidden index 0..63

    __shared__ float sh1[H];
    __shared__ float sred[2];

    const float x = rp[lr];             // Z == 1
    const float p = phi[b * L + l];

    sh1[j] = fmaxf(fmaf(W1[2 * j], x, fmaf(W1[2 * j + 1], p, b1[j])), 0.0f);
    __syncthreads();

    float acc = b2[j];
    const float* w2row = W2 + j * H;
#pragma unroll
    for (int k = 0; k < H; k++)
        acc = fmaf(w2row[k], sh1[k], acc);

    float q = W3[j] * fmaxf(acc, 0.0f);

    // reduce 64 partials: intra-warp shuffles, then combine 2 warps
#pragma unroll
    for (int off = 16; off > 0; off >>= 1)
        q += __shfl_xor_sync(0xffffffffu, q, off);
    if ((j & 31) == 0) sred[j >> 5] = q;
    __syncthreads();
    if (j == 0)
        g_q0[i] = sred[0] + sred[1] + b3[0];
}

// ---------------------------------------------------------------------------
// Kernel 2: expansion. out[b][n][l] = q0[b][l][(n >> 3l) & 7].
// Each thread writes ONE float4 at its own linear position -> fully coalesced.
// float offset f = 4*j within batch b; f mod 6 cycles {0,4,2} with j mod 3,
// giving 3 static element patterns.
// ---------------------------------------------------------------------------
__global__ void __launch_bounds__(256) zdec_expand_kernel(float* __restrict__ out)
{
    __shared__ float sq[L * R];         // 48 values for this b, layout l*8 + digit

    const int b = blockIdx.y;
    if (threadIdx.x < L * R)
        sq[threadIdx.x] = g_q0[b * (L * R) + threadIdx.x];
    __syncthreads();

    const int j   = blockIdx.x * blockDim.x + threadIdx.x;  // float4 idx in b
    const int pat = j % 3;
    const int n   = (2 * j) / 3;        // = (4*j)/6, trajectory index of elem 0

    float4 v;
    if (pat == 0) {
        // floats: (n, l=0..3)
        v.x = sq[       n        & 7];
        v.y = sq[ 8 + ((n >> 3)  & 7)];
        v.z = sq[16 + ((n >> 6)  & 7)];
        v.w = sq[24 + ((n >> 9)  & 7)];
    } else if (pat == 1) {
        // floats: (n, l=4,5), (n+1, l=0,1)
        const int n1 = n + 1;
        v.x = sq[32 + ((n >> 12) & 7)];
        v.y = sq[40 + ((n >> 15) & 7)];
        v.z = sq[       n1       & 7];
        v.w = sq[ 8 + ((n1 >> 3) & 7)];
    } else {
        // floats: (n, l=2..5)
        v.x = sq[16 + ((n >> 6)  & 7)];
        v.y = sq[24 + ((n >> 9)  & 7)];
        v.z = sq[32 + ((n >> 12) & 7)];
        v.w = sq[40 + ((n >> 15) & 7)];
    }

    float4* op = reinterpret_cast<float4*>(out) + (size_t)b * F4_PER_B + j;
    *op = v;
}

// ---------------------------------------------------------------------------
extern "C" void kernel_launch(void* const* d_in, const int* in_sizes, int n_in,
                              void* d_out, int out_size)
{
    const float* phi = (const float*)d_in[0];
    const float* rp  = (const float*)d_in[1];
    const float* W1  = (const float*)d_in[2];
    const float* b1  = (const float*)d_in[3];
    const float* W2  = (const float*)d_in[4];
    const float* b2  = (const float*)d_in[5];
    const float* W3  = (const float*)d_in[6];
    const float* b3  = (const float*)d_in[7];
    float* out = (float*)d_out;

    zdec_mlp_kernel<<<B * L * R, 64>>>(phi, rp, W1, b1, W2, b2, W3, b3);

    dim3 grid(F4_PER_B / 256, B);
    zdec_expand_kernel<<<grid, 256>>>(out);
}

// round 2
// speedup vs baseline: 1.2492x; 1.2492x over previous
#include <cuda_runtime.h>

// Problem constants
#define B 32
#define L 6
#define R 8
#define H 64
#define NTRAJ 262144              // R^L
#define F4_PER_B 393216           // NTRAJ * L / 4
#define TRAJ_PER_BLK 2048         // trajectories per expand block
#define F4_PER_BLK   3072         // TRAJ_PER_BLK * 6 / 4
#define CHUNKS       4            // 512-traj chunks per block

// Scratch for the 1536 MLP outputs q0[b][l][r]
__device__ float g_q0[B * L * R];

// ---------------------------------------------------------------------------
// Kernel 1: tiny MLP. One block per (b,l,r), 64 threads = H lanes.
// ---------------------------------------------------------------------------
__global__ void __launch_bounds__(64) zdec_mlp_kernel(
    const float* __restrict__ phi,   // (B, L)
    const float* __restrict__ rp,    // (L, R, 1)
    const float* __restrict__ W1,    // (H, 2)
    const float* __restrict__ b1,
    const float* __restrict__ W2,    // (H, H)
    const float* __restrict__ b2,
    const float* __restrict__ W3,    // (OUT, H) — row 0 only
    const float* __restrict__ b3)
{
    const int i  = blockIdx.x;          // b*48 + l*8 + r
    const int b  = i / (L * R);
    const int lr = i % (L * R);
    const int l  = lr / R;
    const int j  = threadIdx.x;

    __shared__ float sh1[H];
    __shared__ float sred[2];

    const float x = rp[lr];
    const float p = phi[b * L + l];

    sh1[j] = fmaxf(fmaf(W1[2 * j], x, fmaf(W1[2 * j + 1], p, b1[j])), 0.0f);
    __syncthreads();

    float acc = b2[j];
    const float* w2row = W2 + j * H;
#pragma unroll
    for (int k = 0; k < H; k++)
        acc = fmaf(w2row[k], sh1[k], acc);

    float q = W3[j] * fmaxf(acc, 0.0f);
#pragma unroll
    for (int off = 16; off > 0; off >>= 1)
        q += __shfl_xor_sync(0xffffffffu, q, off);
    if ((j & 31) == 0) sred[j >> 5] = q;
    __syncthreads();
    if (j == 0)
        g_q0[i] = sred[0] + sred[1] + b3[0];
}

// ---------------------------------------------------------------------------
// Kernel 2: expansion. out[b][n][l] = q0[b][l][(n >> 3l) & 7].
//
// Block = (bx, b): covers trajectories n in [bx*2048, bx*2048+2048) of batch b,
// i.e. 3072 coalesced float4s. Split into 4 chunks of 512 trajectories; within
// a chunk the digits for l=3,4,5 are CONSTANT (c3,c4,c5), so only digits 0..2
// need per-f4 shared loads.
//
// Local f4 index jl in [0,768) within a chunk; fl = 4*jl; pat = jl % 3:
//   pat0 (fl%6==0): traj n=2m (even), floats (n,l=0..3)  -> [s[d0], s[8+d1], s[16+d2], c3]
//   pat1 (fl%6==4): n=2m even,        (n,l4),(n,l5),(n+1,l0),(n+1,l1)
//                   d0 even => no carry -> [c4, c5, s[d0+1], s[8+d1]]
//   pat2 (fl%6==2): n=2m+1,           floats (n,l=2..5)  -> [s[16+d2], c3, c4, c5]
// ---------------------------------------------------------------------------
__global__ void __launch_bounds__(256) zdec_expand_kernel(float* __restrict__ out)
{
    __shared__ float sq[L * R];          // 48 values, layout l*8 + digit

    const int b = blockIdx.y;
    if (threadIdx.x < L * R)
        sq[threadIdx.x] = g_q0[b * (L * R) + threadIdx.x];
    __syncthreads();

    const int n_blk = blockIdx.x * TRAJ_PER_BLK;   // traj base of this block
    float4* op = reinterpret_cast<float4*>(out)
               + (size_t)b * F4_PER_B + (size_t)blockIdx.x * F4_PER_BLK;

#pragma unroll
    for (int c = 0; c < CHUNKS; c++) {
        const int nc = n_blk + c * 512;            // chunk traj base (mult of 512)
        const float c3 = sq[24 + ((nc >> 9)  & 7)];
        const float c4 = sq[32 + ((nc >> 12) & 7)];
        const float c5 = sq[40 + ((nc >> 15) & 7)];

#pragma unroll
        for (int s = 0; s < 3; s++) {
            const int jl = s * 256 + threadIdx.x;  // f4 within chunk, 0..767
            const int n  = (2 * jl) / 3;           // local traj within chunk, 0..511
            const int pat = jl % 3;
            const int d0 = n & 7;
            const int d1 = (n >> 3) & 7;
            const int d2 = (n >> 6) & 7;

            float4 v;
            if (pat == 0) {
                v.x = sq[d0];  v.y = sq[8 + d1];  v.z = sq[16 + d2];  v.w = c3;
            } else if (pat == 1) {
                v.x = c4;  v.y = c5;  v.z = sq[d0 + 1];  v.w = sq[8 + d1];
            } else {
                v.x = sq[16 + d2];  v.y = c3;  v.z = c4;  v.w = c5;
            }
            op[c * 768 + jl] = v;
        }
    }
}

// ---------------------------------------------------------------------------
extern "C" void kernel_launch(void* const* d_in, const int* in_sizes, int n_in,
                              void* d_out, int out_size)
{
    const float* phi = (const float*)d_in[0];
    const float* rp  = (const float*)d_in[1];
    const float* W1  = (const float*)d_in[2];
    const float* b1  = (const float*)d_in[3];
    const float* W2  = (const float*)d_in[4];
    const float* b2  = (const float*)d_in[5];
    const float* W3  = (const float*)d_in[6];
    const float* b3  = (const float*)d_in[7];
    float* out = (float*)d_out;

    zdec_mlp_kernel<<<B * L * R, 64>>>(phi, rp, W1, b1, W2, b2, W3, b3);

    dim3 grid(NTRAJ / TRAJ_PER_BLK, B);            // (128, 32)
    zdec_expand_kernel<<<grid, 256>>>(out);
}

// round 4
// speedup vs baseline: 2.0317x; 1.6265x over previous
#include <cuda_runtime.h>

// Problem constants
#define B 32
#define L 6
#define R 8
#define H 64
#define NTRAJ 262144              // R^L
#define F4_PER_B 393216           // NTRAJ * L / 4
#define TRAJ_PER_BLK 4096         // trajectories per expand block
#define F4_PER_BLK   6144         // TRAJ_PER_BLK * 6 / 4
#define CHUNKS       8            // 512-traj chunks per block
#define ITEMS_PER_MLP_BLK 4

// Scratch for the 1536 MLP outputs q0[b][l][r]
__device__ float g_q0[B * L * R];

// ---------------------------------------------------------------------------
// Kernel 1: tiny MLP, 4 items per 256-thread block.
// W2 staged into shared with 65-float row pitch -> conflict-free compute reads
// (bank of sW2[j*65+k] = (j+k)%32, distinct across lanes).
// ---------------------------------------------------------------------------
__global__ void __launch_bounds__(256) zdec_mlp_kernel(
    const float* __restrict__ phi,   // (B, L)
    const float* __restrict__ rp,    // (L, R, 1)
    const float* __restrict__ W1,    // (H, 2)
    const float* __restrict__ b1,
    const float* __restrict__ W2,    // (H, H)
    const float* __restrict__ b2,
    const float* __restrict__ W3,    // (OUT, H) — row 0 only
    const float* __restrict__ b3)
{
    __shared__ float sW2[H * 65];
    __shared__ float sh1[ITEMS_PER_MLP_BLK][H];
    __shared__ float sred[ITEMS_PER_MLP_BLK][2];

    const int tid  = threadIdx.x;
    const int item = tid >> 6;          // 0..3
    const int j    = tid & 63;          // hidden index

    // coalesced W2 stage: thread t loads W2[t], W2[t+256], ...
#pragma unroll
    for (int t = tid; t < H * H; t += 256) {
        const int g = t >> 6, k = t & 63;
        sW2[g * 65 + k] = W2[t];
    }

    const int ii = blockIdx.x * ITEMS_PER_MLP_BLK + item;   // 0..1535
    const int b  = ii / (L * R);
    const int lr = ii % (L * R);
    const int l  = lr / R;

    const float  x  = rp[lr];
    const float  p  = phi[b * L + l];
    const float2 w1 = reinterpret_cast<const float2*>(W1)[j];

    sh1[item][j] = fmaxf(fmaf(w1.x, x, fmaf(w1.y, p, b1[j])), 0.0f);
    __syncthreads();

    float acc = b2[j];
#pragma unroll
    for (int k = 0; k < H; k++)
        acc = fmaf(sW2[j * 65 + k], sh1[item][k], acc);

    float q = W3[j] * fmaxf(acc, 0.0f);
#pragma unroll
    for (int off = 16; off > 0; off >>= 1)
        q += __shfl_xor_sync(0xffffffffu, q, off);
    if ((j & 31) == 0) sred[item][j >> 5] = q;
    __syncthreads();
    if (j == 0)
        g_q0[ii] = sred[item][0] + sred[item][1] + b3[0];
}

// ---------------------------------------------------------------------------
// Kernel 2: expansion. out[b][n][l] = q0[b][l][(n >> 3l) & 7].
// Block = (bx, b): 4096 trajectories = 6144 coalesced float4s, in 8 chunks of
// 512 traj; within a chunk digits l=3,4,5 are constants (c3,c4,c5).
// Streaming stores (__stcs): output is write-once, keep it out of L2's way.
// ---------------------------------------------------------------------------
__global__ void __launch_bounds__(512) zdec_expand_kernel(float* __restrict__ out)
{
    __shared__ float sq[L * R];          // 48 values, layout l*8 + digit

    const int b = blockIdx.y;
    if (threadIdx.x < L * R)
        sq[threadIdx.x] = g_q0[b * (L * R) + threadIdx.x];
    __syncthreads();

    const int n_blk = blockIdx.x * TRAJ_PER_BLK;
    float4* op = reinterpret_cast<float4*>(out)
               + (size_t)b * F4_PER_B + (size_t)blockIdx.x * F4_PER_BLK;

#pragma unroll
    for (int c = 0; c < CHUNKS; c++) {
        const int nc = n_blk + c * 512;            // chunk base (mult of 512)
        const float c3 = sq[24 + ((nc >> 9)  & 7)];
        const float c4 = sq[32 + ((nc >> 12) & 7)];
        const float c5 = sq[40 + ((nc >> 15) & 7)];

        // 768 float4s per chunk; threads 512 -> 1.5 iters; do as 3 half-waves
#pragma unroll
        for (int s = 0; s < 3; s++) {
            const int jl = s * 256 + (threadIdx.x & 255);   // 0..767
            if ((threadIdx.x >> 8) != (s & 1) && s < 2) continue;
            // s=0: lower 256 threads, s=1: upper 256, s=2: all? -- no: restructure
        }
        // (simpler exact mapping below)
#pragma unroll
        for (int s = 0; s < 3; s += 2) {
            // iteration A: jl = threadIdx.x + s*512 covers [0,512) and [1024?..)
        }
        // --- actual loop: 6144/512 threads, jl = t, t+512, t+... per chunk is 768
        // handled outside; see below
        (void)c3; (void)c4; (void)c5; (void)nc; (void)op;
        break; // placeholder removed below
    }

    // Clean implementation: iterate over the block's 6144 float4s directly.
    // jl_blk in [0,6144): chunk = jl_blk/768, within-chunk f4 = jl_blk%768.
#pragma unroll
    for (int it = 0; it < F4_PER_BLK / 512; it++) {
        const int jl_blk = it * 512 + threadIdx.x;
        const int ch  = jl_blk / 768;
        const int jl  = jl_blk - ch * 768;         // 0..767 within chunk
        const int nc  = n_blk + ch * 512;
        const float c3 = sq[24 + ((nc >> 9)  & 7)];
        const float c4 = sq[32 + ((nc >> 12) & 7)];
        const float c5 = sq[40 + ((nc >> 15) & 7)];

        const int n   = (2 * jl) / 3;              // local traj 0..511
        const int pat = jl % 3;
        const int d0 = n & 7;
        const int d1 = (n >> 3) & 7;
        const int d2 = (n >> 6) & 7;

        float4 v;
        if (pat == 0) {
            v.x = sq[d0];  v.y = sq[8 + d1];  v.z = sq[16 + d2];  v.w = c3;
        } else if (pat == 1) {
            v.x = c4;  v.y = c5;  v.z = sq[d0 + 1];  v.w = sq[8 + d1];
        } else {
            v.x = sq[16 + d2];  v.y = c3;  v.z = c4;  v.w = c5;
        }
        __stcs(op + jl_blk, v);
    }
}

// ---------------------------------------------------------------------------
extern "C" void kernel_launch(void* const* d_in, const int* in_sizes, int n_in,
                              void* d_out, int out_size)
{
    const float* phi = (const float*)d_in[0];
    const float* rp  = (const float*)d_in[1];
    const float* W1  = (const float*)d_in[2];
    const float* b1  = (const float*)d_in[3];
    const float* W2  = (const float*)d_in[4];
    const float* b2  = (const float*)d_in[5];
    const float* W3  = (const float*)d_in[6];
    const float* b3  = (const float*)d_in[7];
    float* out = (float*)d_out;

    zdec_mlp_kernel<<<(B * L * R) / ITEMS_PER_MLP_BLK, 256>>>(
        phi, rp, W1, b1, W2, b2, W3, b3);

    dim3 grid(NTRAJ / TRAJ_PER_BLK, B);            // (64, 32)
    zdec_expand_kernel<<<grid, 512>>>(out);
}